// round 16
// baseline (speedup 1.0000x reference)
#include <cuda_runtime.h>
#include <cuda_fp16.h>
#include <cstdint>

#define B_   8
#define LQ_  2048
#define LK_  2048
#define DW_  1024
#define DP_  128
#define INV_T 0.08838834764831845f
#define NSPLIT 4

typedef uint32_t u32;

// ---------------- device scratch (no runtime alloc) ----------------
__device__ __half g_w[3][DW_][DP_];                    // W single fp16 [z][k][n]
__device__ __half g_q[(size_t)B_*LQ_*DP_];             // Q single [tok][d]
__device__ __half g_kt[(size_t)B_*DP_*LK_];            // K^T single [b][d][tok]
__device__ __half g_vt[(size_t)B_*DP_*LK_];            // V^T single [b][d][tok]
__device__ u32 g_po[NSPLIT][(size_t)B_*LQ_*DP_/2];     // partial O, packed fp16 pairs
__device__ float g_pl[NSPLIT][B_*LQ_];                 // partial row sums
__device__ int g_ctr[B_][16];                          // arrival counters (zero-init; reset by combiner)

// ---------------- helpers ----------------
__device__ __forceinline__ u32 s2u(const void* p) {
    u32 a;
    asm("{ .reg .u64 t; cvta.to.shared.u64 t, %1; cvt.u32.u64 %0, t; }" : "=r"(a) : "l"(p));
    return a;
}
// fp16 single pack (lo half = a, hi half = b)
__device__ __forceinline__ u32 pk1(float a, float b) {
    u32 r;
    asm("cvt.rn.f16x2.f32 %0, %1, %2;" : "=r"(r) : "f"(b), "f"(a));
    return r;
}
__device__ __forceinline__ void ldsm4(u32* r, u32 a) {
    asm volatile("ldmatrix.sync.aligned.m8n8.x4.shared.b16 {%0,%1,%2,%3}, [%4];"
        : "=r"(r[0]), "=r"(r[1]), "=r"(r[2]), "=r"(r[3]) : "r"(a));
}
__device__ __forceinline__ void ldsm4t(u32* r, u32 a) {
    asm volatile("ldmatrix.sync.aligned.m8n8.x4.trans.shared.b16 {%0,%1,%2,%3}, [%4];"
        : "=r"(r[0]), "=r"(r[1]), "=r"(r[2]), "=r"(r[3]) : "r"(a));
}
__device__ __forceinline__ void mmaf(float* c, const u32* a, const u32* b) {
    asm volatile("mma.sync.aligned.m16n8k16.row.col.f32.f16.f16.f32 "
        "{%0,%1,%2,%3}, {%4,%5,%6,%7}, {%8,%9}, {%0,%1,%2,%3};"
        : "+f"(c[0]), "+f"(c[1]), "+f"(c[2]), "+f"(c[3])
        : "r"(a[0]), "r"(a[1]), "r"(a[2]), "r"(a[3]), "r"(b[0]), "r"(b[1]));
}
#define CPA(dst, src) asm volatile("cp.async.ca.shared.global [%0], [%1], 16;" :: "r"(dst), "l"(src) : "memory")
#define CPC()   asm volatile("cp.async.commit_group;" ::: "memory")
#define CPW(n)  asm volatile("cp.async.wait_group %0;" :: "n"(n) : "memory")

// ---------------- W prep: single fp16, fold 1/T into Wq ----------------
__global__ void __launch_bounds__(256, 4) wprep_kernel(
    const float* __restrict__ Wq, const float* __restrict__ Wk, const float* __restrict__ Wv)
{
    const int z = blockIdx.y;
    const int idx = blockIdx.x * 256 + threadIdx.x;     // 0..65535
    const int k = idx >> 6, n2 = (idx & 63) * 2;
    const float* W = (z == 0) ? Wq : (z == 1) ? Wk : Wv;
    const float sc = (z == 0) ? INV_T : 1.0f;
    float x0 = W[(size_t)k * DP_ + n2]     * sc;
    float x1 = W[(size_t)k * DP_ + n2 + 1] * sc;
    *(u32*)&g_w[z][k][n2] = pk1(x0, x1);
}

// ---------------- projection GEMM (LDG-direct A, 1 sync/stage, fp16 single-pass) ----------------
// grid (128, 3), 256 thr, 2 CTA/SM. BM=128, BN=128, BK=32, warps 2(m)x4(n), warp tile 64x32.
#define AB(b)  ((b) * 10240)
#define WB(b)  (20480 + (b) * 8704)
#define PJ_SM 37888

__global__ void __launch_bounds__(256, 2) proj_mma(
    const float* __restrict__ q, const float* __restrict__ k, const float* __restrict__ v)
{
    extern __shared__ char smem[];
    const u32 sb = s2u(smem);
    const int tid = threadIdx.x, wid = tid >> 5, lane = tid & 31;
    const int wm = wid >> 2, wn = wid & 3;
    const int z = blockIdx.y;
    const int m0 = blockIdx.x * 128;
    const float* A = (z == 0) ? q : (z == 1) ? k : v;
    const __half* Wg = &g_w[z][0][0];

    float acc[4][4][4];
    #pragma unroll
    for (int a = 0; a < 4; a++)
        #pragma unroll
        for (int b = 0; b < 4; b++)
            #pragma unroll
            for (int c = 0; c < 4; c++) acc[a][b][c] = 0.0f;

    const int arow = tid >> 3, acol = tid & 7;          // A: row 0..31 base, col chunk
    float4 av[4];
    // preload A(0) into regs; issue W(0)
    #pragma unroll
    for (int h = 0; h < 4; h++)
        av[h] = *(const float4*)&A[(size_t)(m0 + arow + h * 32) * DW_ + acol * 4];
    #pragma unroll
    for (int h = 0; h < 2; h++) {
        int g = tid + h * 256, row = g >> 4, c = g & 15;
        CPA(sb + WB(0) + row * 272 + c * 16, (const char*)(Wg + (size_t)row * DP_) + c * 16);
    }
    CPC();

    const int rsel = ((lane >> 3) & 1) * 8 + (lane & 7);
    const int bsel = ((lane >> 4) & 1) * 16;

    #pragma unroll 1
    for (int s = 0; s < 32; s++) {
        const int buf = s & 1;
        // STS pack A(s) from regs
        #pragma unroll
        for (int h = 0; h < 4; h++) {
            u32 hi0 = pk1(av[h].x, av[h].y);
            u32 hi1 = pk1(av[h].z, av[h].w);
            *(uint2*)(smem + AB(buf) + (arow + h * 32) * 80 + acol * 8) = make_uint2(hi0, hi1);
        }
        CPW(0);                 // W(s) arrived
        __syncthreads();        // separates compute(s-1) from overwrites; publishes A(s)
        if (s + 1 < 32) {
            const int kb = (s + 1) * 32, nb = buf ^ 1;
            #pragma unroll
            for (int h = 0; h < 2; h++) {
                int g = tid + h * 256, row = g >> 4, c = g & 15;
                CPA(sb + WB(nb) + row * 272 + c * 16, (const char*)(Wg + (size_t)(kb + row) * DP_) + c * 16);
            }
            CPC();
            #pragma unroll
            for (int h = 0; h < 4; h++)
                av[h] = *(const float4*)&A[(size_t)(m0 + arow + h * 32) * DW_ + kb + acol * 4];
        }
        // compute stage s
        #pragma unroll
        for (int ks = 0; ks < 2; ks++) {
            u32 bh[2][4];
            #pragma unroll
            for (int ng = 0; ng < 2; ng++) {
                u32 krow = ks * 16 + rsel;
                u32 byt = wn * 64 + ng * 32 + bsel;
                ldsm4t(bh[ng], sb + WB(buf) + krow * 272 + byt);
            }
            #pragma unroll
            for (int mt = 0; mt < 4; mt++) {
                u32 ah[4];
                u32 row = wm * 64 + mt * 16 + rsel;
                u32 byt = ks * 32 + bsel;
                ldsm4(ah, sb + AB(buf) + row * 80 + byt);
                #pragma unroll
                for (int nt = 0; nt < 4; nt++)
                    mmaf(acc[mt][nt], ah, &bh[nt >> 1][(nt & 1) * 2]);
            }
        }
    }

    // epilogue: stage through smem per n-half, single fp16 outputs
    #pragma unroll 1
    for (int nh = 0; nh < 2; nh++) {
        __syncthreads();
        if ((wn >> 1) == nh) {
            #pragma unroll
            for (int mt = 0; mt < 4; mt++)
                #pragma unroll
                for (int nt = 0; nt < 4; nt++) {
                    int m = wm * 64 + mt * 16 + (lane >> 2);
                    int nl = (wn & 1) * 32 + nt * 8 + (lane & 3) * 2;
                    if (z == 0) {
                        *(u32*)(smem + m * 144 + nl * 2)       = pk1(acc[mt][nt][0], acc[mt][nt][1]);
                        *(u32*)(smem + (m + 8) * 144 + nl * 2) = pk1(acc[mt][nt][2], acc[mt][nt][3]);
                    } else {
                        // transposed staging [nl][m]
                        *(__half*)(smem + nl * 272 + m * 2)             = __float2half_rn(acc[mt][nt][0]);
                        *(__half*)(smem + (nl + 1) * 272 + m * 2)       = __float2half_rn(acc[mt][nt][1]);
                        *(__half*)(smem + nl * 272 + (m + 8) * 2)       = __float2half_rn(acc[mt][nt][2]);
                        *(__half*)(smem + (nl + 1) * 272 + (m + 8) * 2) = __float2half_rn(acc[mt][nt][3]);
                    }
                }
        }
        __syncthreads();
        if (z == 0) {
            int m = tid >> 1, h2 = tid & 1;
            char* dQ = (char*)g_q + ((size_t)(m0 + m) * DP_ + nh * 64 + h2 * 32) * 2;
            #pragma unroll
            for (int i = 0; i < 4; i++)
                *(uint4*)(dQ + i * 16) = *(uint4*)(smem + m * 144 + h2 * 64 + i * 16);
        } else {
            __half* G = (z == 1) ? g_kt : g_vt;
            const int bb = m0 >> 11, t0 = m0 & 2047;
            int nl = tid >> 2, q4 = tid & 3;
            char* dG = (char*)G + ((size_t)(bb * 128 + nh * 64 + nl) * 2048 + t0 + q4 * 32) * 2;
            #pragma unroll
            for (int i = 0; i < 4; i++)
                *(uint4*)(dG + i * 16) = *(uint4*)(smem + nl * 272 + q4 * 64 + i * 16);
        }
    }
}

// ---------------- flash attention (fused split-combine) ----------------
// grid (16, 8, 4), 256 thr. 128 q rows/CTA, TK=64, each CTA <=8 k-tiles.
// ns==1: write out directly. ns>1: partials + last CTA combines (threadfence reduction).
#define AQ 0
#define ABUF(b) (34816 + (b) * 36864)
#define AK(b) (ABUF(b))
#define AV(b) (ABUF(b) + 18432)
#define A_SM 108544

__global__ void __launch_bounds__(256, 1) attn_mma(
    const int* __restrict__ memlen_arr, float* __restrict__ out)
{
    extern __shared__ char smem[];
    const u32 sb = s2u(smem);
    const int tid = threadIdx.x, wid = tid >> 5, lane = tid & 31;
    const int b = blockIdx.y;
    const int q0 = blockIdx.x * 128;
    const int kh = blockIdx.z;
    const int memlen = memlen_arr[b];
    const int ntiles = (memlen + 63) >> 6;
    const int ns = (ntiles + 7) >> 3;                   // used splits for this batch
    const int tb = kh * 8;
    const int te = (ntiles < tb + 8) ? ntiles : (tb + 8);

    if (tb >= te) return;

    // Q loads (single fp16)
    #pragma unroll
    for (int h = 0; h < 4; h++) {
        int f = tid + h * 256, row = f >> 3, c = f & 7;
        const char* sQ = (const char*)g_q + ((size_t)(b * LQ_ + q0 + row) * DP_ + c * 16) * 2;
        CPA(sb + AQ + row * 272 + c * 32, sQ);
        CPA(sb + AQ + row * 272 + c * 32 + 16, sQ + 16);
    }
    CPC();
    // K/V tile tb
    #pragma unroll
    for (int h = 0; h < 4; h++) {
        int f = tid + h * 256, d = f >> 3, c = f & 7;
        size_t g = ((size_t)(b * 128 + d) * 2048 + tb * 64 + c * 8) * 2;
        CPA(sb + AK(0) + d * 144 + c * 16, (const char*)g_kt + g);
        CPA(sb + AV(0) + d * 144 + c * 16, (const char*)g_vt + g);
    }
    CPC();

    float o[16][4];
    #pragma unroll
    for (int a = 0; a < 16; a++)
        #pragma unroll
        for (int c = 0; c < 4; c++) o[a][c] = 0.0f;
    float lsum0 = 0.0f, lsum1 = 0.0f;

    const int rsel = ((lane >> 3) & 1) * 8 + (lane & 7);
    const int bsel = ((lane >> 4) & 1) * 16;
    const int vrsel = ((lane >> 4) & 1) * 8 + (lane & 7);
    const int vbsel = ((lane >> 3) & 1) * 16;

    for (int t = tb; t < te; t++) {
        const int buf = (t - tb) & 1;
        const int k0 = t * 64;
        if (t + 1 < te) {
            const int k1 = (t + 1) * 64;
            #pragma unroll
            for (int h = 0; h < 4; h++) {
                int f = tid + h * 256, d = f >> 3, c = f & 7;
                size_t g = ((size_t)(b * 128 + d) * 2048 + k1 + c * 8) * 2;
                CPA(sb + AK(buf ^ 1) + d * 144 + c * 16, (const char*)g_kt + g);
                CPA(sb + AV(buf ^ 1) + d * 144 + c * 16, (const char*)g_vt + g);
            }
            CPC();
            CPW(1);
        } else {
            CPW(0);
        }
        __syncthreads();

        // ---- S = Q K^T (single pass) ----
        float s[8][4];
        #pragma unroll
        for (int a = 0; a < 8; a++)
            #pragma unroll
            for (int c = 0; c < 4; c++) s[a][c] = 0.0f;
        #pragma unroll
        for (int ks = 0; ks < 8; ks++) {
            u32 qf[4];
            {
                u32 row = wid * 16 + rsel;
                u32 byt = ks * 32 + bsel;
                ldsm4(qf, sb + AQ + row * 272 + byt);
            }
            u32 kf[4][4];
            #pragma unroll
            for (int g = 0; g < 4; g++) {
                u32 krow = ks * 16 + rsel;
                u32 byt = g * 32 + bsel;
                ldsm4t(kf[g], sb + AK(buf) + krow * 144 + byt);
            }
            #pragma unroll
            for (int nt = 0; nt < 8; nt++)
                mmaf(s[nt], qf, &kf[nt >> 1][(nt & 1) * 2]);
        }

        // ---- softmax (no max; exp-safe), pack P single fp16 ----
        const int nvalid = memlen - k0;
        u32 pf[4][4];
        #pragma unroll
        for (int nt = 0; nt < 8; nt++) {
            int j0 = nt * 8 + (lane & 3) * 2;
            float p0 = (j0     < nvalid) ? __expf(s[nt][0]) : 0.0f;
            float p1 = (j0 + 1 < nvalid) ? __expf(s[nt][1]) : 0.0f;
            float p2 = (j0     < nvalid) ? __expf(s[nt][2]) : 0.0f;
            float p3 = (j0 + 1 < nvalid) ? __expf(s[nt][3]) : 0.0f;
            lsum0 += p0 + p1;
            lsum1 += p2 + p3;
            int kt = nt >> 1, half = nt & 1;
            pf[kt][half * 2 + 0] = pk1(p0, p1);
            pf[kt][half * 2 + 1] = pk1(p2, p3);
        }

        // ---- O += P V (single pass) ----
        #pragma unroll
        for (int kt = 0; kt < 4; kt++) {
            #pragma unroll
            for (int nd = 0; nd < 8; nd++) {
                u32 vh[4];
                u32 row = nd * 16 + vrsel;
                u32 byt = kt * 32 + vbsel;
                ldsm4(vh, sb + AV(buf) + row * 144 + byt);
                mmaf(o[2 * nd],     pf[kt], vh);
                mmaf(o[2 * nd + 1], pf[kt], vh + 2);
            }
        }
        __syncthreads();
    }

    // ---- row-sum reduce across the 4 lanes of each row ----
    lsum0 += __shfl_xor_sync(0xffffffffu, lsum0, 1);
    lsum0 += __shfl_xor_sync(0xffffffffu, lsum0, 2);
    lsum1 += __shfl_xor_sync(0xffffffffu, lsum1, 1);
    lsum1 += __shfl_xor_sync(0xffffffffu, lsum1, 2);
    const int r = q0 + wid * 16 + (lane >> 2);

    if (ns == 1) {
        // single split: write normalized output directly
        const float inv0 = 1.0f / lsum0, inv1 = 1.0f / lsum1;
        #pragma unroll
        for (int nt = 0; nt < 16; nt++) {
            int c = nt * 8 + (lane & 3) * 2;
            *(float2*)&out[(size_t)(b * LQ_ + r) * DP_ + c]     = make_float2(o[nt][0] * inv0, o[nt][1] * inv0);
            *(float2*)&out[(size_t)(b * LQ_ + r + 8) * DP_ + c] = make_float2(o[nt][2] * inv1, o[nt][3] * inv1);
        }
        return;
    }

    // ---- multi-split: write fp16 partials, last CTA combines ----
    #pragma unroll
    for (int nt = 0; nt < 16; nt++) {
        int c = nt * 8 + (lane & 3) * 2;
        g_po[kh][((size_t)(b * LQ_ + r) * DP_ + c) >> 1]     = pk1(o[nt][0], o[nt][1]);
        g_po[kh][((size_t)(b * LQ_ + r + 8) * DP_ + c) >> 1] = pk1(o[nt][2], o[nt][3]);
    }
    if ((lane & 3) == 0) {
        g_pl[kh][b * LQ_ + r]     = lsum0;
        g_pl[kh][b * LQ_ + r + 8] = lsum1;
    }
    __threadfence();
    __syncthreads();
    volatile int* flag = (volatile int*)smem;
    if (tid == 0)
        *flag = (atomicAdd(&g_ctr[b][blockIdx.x], 1) == ns - 1) ? 1 : 0;
    __syncthreads();
    if (*flag) {
        // this CTA is last: combine all ns partials for rows [q0, q0+128)
        __threadfence();   // order partial reads after observing all arrivals
        #pragma unroll 1
        for (int idx = tid; idx < 128 * 32; idx += 256) {   // float4 units
            int rl = idx >> 5, c4 = idx & 31;
            size_t row = (size_t)(b * LQ_ + q0 + rl);
            float l = 0.0f;
            float4 w = make_float4(0.f, 0.f, 0.f, 0.f);
            #pragma unroll 1
            for (int s2 = 0; s2 < ns; s2++) {
                l += g_pl[s2][row];
                uint2 a = *(const uint2*)&g_po[s2][(row * DP_ + c4 * 4) >> 1];
                __half2 h0 = *reinterpret_cast<__half2*>(&a.x);
                __half2 h1 = *reinterpret_cast<__half2*>(&a.y);
                w.x += __low2float(h0); w.y += __high2float(h0);
                w.z += __low2float(h1); w.w += __high2float(h1);
            }
            const float inv = 1.0f / l;
            w.x *= inv; w.y *= inv; w.z *= inv; w.w *= inv;
            *(float4*)&out[row * DP_ + c4 * 4] = w;
        }
        __syncthreads();
        if (tid == 0) g_ctr[b][blockIdx.x] = 0;   // reset for next graph replay
    }
}

// ---------------- launch ----------------
extern "C" void kernel_launch(void* const* d_in, const int* in_sizes, int n_in,
                              void* d_out, int out_size)
{
    const float* q  = (const float*)d_in[0];
    const float* k  = (const float*)d_in[1];
    const float* v  = (const float*)d_in[2];
    const int* memlen = (const int*)d_in[3];
    const float* Wq = (const float*)d_in[4];
    const float* Wk = (const float*)d_in[5];
    const float* Wv = (const float*)d_in[6];
    float* out = (float*)d_out;

    dim3 wgrid(256, 3);
    wprep_kernel<<<wgrid, 256>>>(Wq, Wk, Wv);

    cudaFuncSetAttribute(proj_mma, cudaFuncAttributeMaxDynamicSharedMemorySize, PJ_SM);
    dim3 pgrid(128, 3);
    proj_mma<<<pgrid, 256, PJ_SM>>>(q, k, v);

    cudaFuncSetAttribute(attn_mma, cudaFuncAttributeMaxDynamicSharedMemorySize, A_SM);
    dim3 agrid(16, 8, NSPLIT);
    attn_mma<<<agrid, 256, A_SM>>>(memlen, out);
}

// round 17
// speedup vs baseline: 1.5963x; 1.5963x over previous
#include <cuda_runtime.h>
#include <cuda_fp16.h>
#include <cstdint>

#define B_   8
#define LQ_  2048
#define LK_  2048
#define DW_  1024
#define DP_  128
#define INV_T 0.08838834764831845f
#define NSPLIT 4

typedef uint32_t u32;

// ---------------- device scratch (no runtime alloc) ----------------
__device__ __half g_w[3][DW_][DP_];                    // W single fp16 [z][k][n]
__device__ __half g_q[(size_t)B_*LQ_*DP_];             // Q single [tok][d]
__device__ __half g_kt[(size_t)B_*DP_*LK_];            // K^T single [b][d][tok]
__device__ __half g_vt[(size_t)B_*DP_*LK_];            // V^T single [b][d][tok]
__device__ u32 g_po[NSPLIT][(size_t)B_*LQ_*DP_/2];     // partial O, packed fp16 pairs
__device__ float g_pl[NSPLIT][B_*LQ_];                 // partial row sums

// ---------------- helpers ----------------
__device__ __forceinline__ u32 s2u(const void* p) {
    u32 a;
    asm("{ .reg .u64 t; cvta.to.shared.u64 t, %1; cvt.u32.u64 %0, t; }" : "=r"(a) : "l"(p));
    return a;
}
// fp16 single pack (lo half = a, hi half = b)
__device__ __forceinline__ u32 pk1(float a, float b) {
    u32 r;
    asm("cvt.rn.f16x2.f32 %0, %1, %2;" : "=r"(r) : "f"(b), "f"(a));
    return r;
}
__device__ __forceinline__ void ldsm4(u32* r, u32 a) {
    asm volatile("ldmatrix.sync.aligned.m8n8.x4.shared.b16 {%0,%1,%2,%3}, [%4];"
        : "=r"(r[0]), "=r"(r[1]), "=r"(r[2]), "=r"(r[3]) : "r"(a));
}
__device__ __forceinline__ void ldsm4t(u32* r, u32 a) {
    asm volatile("ldmatrix.sync.aligned.m8n8.x4.trans.shared.b16 {%0,%1,%2,%3}, [%4];"
        : "=r"(r[0]), "=r"(r[1]), "=r"(r[2]), "=r"(r[3]) : "r"(a));
}
__device__ __forceinline__ void mmaf(float* c, const u32* a, const u32* b) {
    asm volatile("mma.sync.aligned.m16n8k16.row.col.f32.f16.f16.f32 "
        "{%0,%1,%2,%3}, {%4,%5,%6,%7}, {%8,%9}, {%0,%1,%2,%3};"
        : "+f"(c[0]), "+f"(c[1]), "+f"(c[2]), "+f"(c[3])
        : "r"(a[0]), "r"(a[1]), "r"(a[2]), "r"(a[3]), "r"(b[0]), "r"(b[1]));
}
#define CPA(dst, src) asm volatile("cp.async.ca.shared.global [%0], [%1], 16;" :: "r"(dst), "l"(src) : "memory")
#define CPC()   asm volatile("cp.async.commit_group;" ::: "memory")
#define CPW(n)  asm volatile("cp.async.wait_group %0;" :: "n"(n) : "memory")

// ---------------- W prep: single fp16, fold 1/T into Wq (4 elems/thread) ----------------
__global__ void __launch_bounds__(256, 4) wprep_kernel(
    const float* __restrict__ Wq, const float* __restrict__ Wk, const float* __restrict__ Wv)
{
    const int z = blockIdx.y;
    const int idx = blockIdx.x * 256 + threadIdx.x;     // 0..32767
    const int k = idx >> 5, n4 = (idx & 31) * 4;
    const float* W = (z == 0) ? Wq : (z == 1) ? Wk : Wv;
    const float sc = (z == 0) ? INV_T : 1.0f;
    float4 x = *(const float4*)&W[(size_t)k * DP_ + n4];
    u32 h0 = pk1(x.x * sc, x.y * sc);
    u32 h1 = pk1(x.z * sc, x.w * sc);
    *(uint2*)&g_w[z][k][n4] = make_uint2(h0, h1);
}

// ---------------- projection GEMM (LDG-direct A, 1 sync/stage, fp16 single-pass) ----------------
// grid (128, 3), 256 thr, 2 CTA/SM. BM=128, BN=128, BK=32, warps 2(m)x4(n), warp tile 64x32.
// K/V row-tiles entirely beyond memlen[b] are skipped (their outputs are never read unmasked).
#define AB(b)  ((b) * 10240)
#define WB(b)  (20480 + (b) * 8704)
#define PJ_SM 37888

__global__ void __launch_bounds__(256, 2) proj_mma(
    const float* __restrict__ q, const float* __restrict__ k, const float* __restrict__ v,
    const int* __restrict__ memlen_arr)
{
    extern __shared__ char smem[];
    const u32 sb = s2u(smem);
    const int tid = threadIdx.x, wid = tid >> 5, lane = tid & 31;
    const int wm = wid >> 2, wn = wid & 3;
    const int z = blockIdx.y;
    const int m0 = blockIdx.x * 128;

    // dead-work skip: K/V rows at-or-beyond memlen are masked out downstream
    if (z > 0) {
        const int bb = m0 >> 11, t0 = m0 & 2047;
        if (t0 >= memlen_arr[bb]) return;
    }

    const float* A = (z == 0) ? q : (z == 1) ? k : v;
    const __half* Wg = &g_w[z][0][0];

    float acc[4][4][4];
    #pragma unroll
    for (int a = 0; a < 4; a++)
        #pragma unroll
        for (int b = 0; b < 4; b++)
            #pragma unroll
            for (int c = 0; c < 4; c++) acc[a][b][c] = 0.0f;

    const int arow = tid >> 3, acol = tid & 7;          // A: row 0..31 base, col chunk
    float4 av[4];
    // preload A(0) into regs; issue W(0)
    #pragma unroll
    for (int h = 0; h < 4; h++)
        av[h] = *(const float4*)&A[(size_t)(m0 + arow + h * 32) * DW_ + acol * 4];
    #pragma unroll
    for (int h = 0; h < 2; h++) {
        int g = tid + h * 256, row = g >> 4, c = g & 15;
        CPA(sb + WB(0) + row * 272 + c * 16, (const char*)(Wg + (size_t)row * DP_) + c * 16);
    }
    CPC();

    const int rsel = ((lane >> 3) & 1) * 8 + (lane & 7);
    const int bsel = ((lane >> 4) & 1) * 16;

    #pragma unroll 1
    for (int s = 0; s < 32; s++) {
        const int buf = s & 1;
        // STS pack A(s) from regs
        #pragma unroll
        for (int h = 0; h < 4; h++) {
            u32 hi0 = pk1(av[h].x, av[h].y);
            u32 hi1 = pk1(av[h].z, av[h].w);
            *(uint2*)(smem + AB(buf) + (arow + h * 32) * 80 + acol * 8) = make_uint2(hi0, hi1);
        }
        CPW(0);                 // W(s) arrived
        __syncthreads();        // separates compute(s-1) from overwrites; publishes A(s)
        if (s + 1 < 32) {
            const int kb = (s + 1) * 32, nb = buf ^ 1;
            #pragma unroll
            for (int h = 0; h < 2; h++) {
                int g = tid + h * 256, row = g >> 4, c = g & 15;
                CPA(sb + WB(nb) + row * 272 + c * 16, (const char*)(Wg + (size_t)(kb + row) * DP_) + c * 16);
            }
            CPC();
            #pragma unroll
            for (int h = 0; h < 4; h++)
                av[h] = *(const float4*)&A[(size_t)(m0 + arow + h * 32) * DW_ + kb + acol * 4];
        }
        // compute stage s
        #pragma unroll
        for (int ks = 0; ks < 2; ks++) {
            u32 bh[2][4];
            #pragma unroll
            for (int ng = 0; ng < 2; ng++) {
                u32 krow = ks * 16 + rsel;
                u32 byt = wn * 64 + ng * 32 + bsel;
                ldsm4t(bh[ng], sb + WB(buf) + krow * 272 + byt);
            }
            #pragma unroll
            for (int mt = 0; mt < 4; mt++) {
                u32 ah[4];
                u32 row = wm * 64 + mt * 16 + rsel;
                u32 byt = ks * 32 + bsel;
                ldsm4(ah, sb + AB(buf) + row * 80 + byt);
                #pragma unroll
                for (int nt = 0; nt < 4; nt++)
                    mmaf(acc[mt][nt], ah, &bh[nt >> 1][(nt & 1) * 2]);
            }
        }
    }

    // epilogue: stage through smem per n-half, single fp16 outputs
    #pragma unroll 1
    for (int nh = 0; nh < 2; nh++) {
        __syncthreads();
        if ((wn >> 1) == nh) {
            #pragma unroll
            for (int mt = 0; mt < 4; mt++)
                #pragma unroll
                for (int nt = 0; nt < 4; nt++) {
                    int m = wm * 64 + mt * 16 + (lane >> 2);
                    int nl = (wn & 1) * 32 + nt * 8 + (lane & 3) * 2;
                    if (z == 0) {
                        *(u32*)(smem + m * 144 + nl * 2)       = pk1(acc[mt][nt][0], acc[mt][nt][1]);
                        *(u32*)(smem + (m + 8) * 144 + nl * 2) = pk1(acc[mt][nt][2], acc[mt][nt][3]);
                    } else {
                        // transposed staging [nl][m]
                        *(__half*)(smem + nl * 272 + m * 2)             = __float2half_rn(acc[mt][nt][0]);
                        *(__half*)(smem + (nl + 1) * 272 + m * 2)       = __float2half_rn(acc[mt][nt][1]);
                        *(__half*)(smem + nl * 272 + (m + 8) * 2)       = __float2half_rn(acc[mt][nt][2]);
                        *(__half*)(smem + (nl + 1) * 272 + (m + 8) * 2) = __float2half_rn(acc[mt][nt][3]);
                    }
                }
        }
        __syncthreads();
        if (z == 0) {
            int m = tid >> 1, h2 = tid & 1;
            char* dQ = (char*)g_q + ((size_t)(m0 + m) * DP_ + nh * 64 + h2 * 32) * 2;
            #pragma unroll
            for (int i = 0; i < 4; i++)
                *(uint4*)(dQ + i * 16) = *(uint4*)(smem + m * 144 + h2 * 64 + i * 16);
        } else {
            __half* G = (z == 1) ? g_kt : g_vt;
            const int bb = m0 >> 11, t0 = m0 & 2047;
            int nl = tid >> 2, q4 = tid & 3;
            char* dG = (char*)G + ((size_t)(bb * 128 + nh * 64 + nl) * 2048 + t0 + q4 * 32) * 2;
            #pragma unroll
            for (int i = 0; i < 4; i++)
                *(uint4*)(dG + i * 16) = *(uint4*)(smem + nl * 272 + q4 * 64 + i * 16);
        }
    }
}

// ---------------- flash attention (fp16 single-pass S and PV; 4-way k-split) ----------------
// grid (16, 8, 4), 256 thr. 128 q rows/CTA, TK=64, each CTA <=8 k-tiles.
#define AQ 0
#define ABUF(b) (34816 + (b) * 36864)
#define AK(b) (ABUF(b))
#define AV(b) (ABUF(b) + 18432)
#define A_SM 108544

__global__ void __launch_bounds__(256, 1) attn_mma(const int* __restrict__ memlen_arr)
{
    extern __shared__ char smem[];
    const u32 sb = s2u(smem);
    const int tid = threadIdx.x, wid = tid >> 5, lane = tid & 31;
    const int b = blockIdx.y;
    const int q0 = blockIdx.x * 128;
    const int kh = blockIdx.z;
    const int memlen = memlen_arr[b];
    const int ntiles = (memlen + 63) >> 6;
    const int tb = kh * 8;
    const int te = (ntiles < tb + 8) ? ntiles : (tb + 8);

    if (tb >= te) return;   // combine skips unused splits

    // Q loads (single fp16)
    #pragma unroll
    for (int h = 0; h < 4; h++) {
        int f = tid + h * 256, row = f >> 3, c = f & 7;
        const char* sQ = (const char*)g_q + ((size_t)(b * LQ_ + q0 + row) * DP_ + c * 16) * 2;
        CPA(sb + AQ + row * 272 + c * 32, sQ);
        CPA(sb + AQ + row * 272 + c * 32 + 16, sQ + 16);
    }
    CPC();
    // K/V tile tb
    #pragma unroll
    for (int h = 0; h < 4; h++) {
        int f = tid + h * 256, d = f >> 3, c = f & 7;
        size_t g = ((size_t)(b * 128 + d) * 2048 + tb * 64 + c * 8) * 2;
        CPA(sb + AK(0) + d * 144 + c * 16, (const char*)g_kt + g);
        CPA(sb + AV(0) + d * 144 + c * 16, (const char*)g_vt + g);
    }
    CPC();

    float o[16][4];
    #pragma unroll
    for (int a = 0; a < 16; a++)
        #pragma unroll
        for (int c = 0; c < 4; c++) o[a][c] = 0.0f;
    float lsum0 = 0.0f, lsum1 = 0.0f;

    const int rsel = ((lane >> 3) & 1) * 8 + (lane & 7);
    const int bsel = ((lane >> 4) & 1) * 16;
    const int vrsel = ((lane >> 4) & 1) * 8 + (lane & 7);
    const int vbsel = ((lane >> 3) & 1) * 16;

    for (int t = tb; t < te; t++) {
        const int buf = (t - tb) & 1;
        const int k0 = t * 64;
        if (t + 1 < te) {
            const int k1 = (t + 1) * 64;
            #pragma unroll
            for (int h = 0; h < 4; h++) {
                int f = tid + h * 256, d = f >> 3, c = f & 7;
                size_t g = ((size_t)(b * 128 + d) * 2048 + k1 + c * 8) * 2;
                CPA(sb + AK(buf ^ 1) + d * 144 + c * 16, (const char*)g_kt + g);
                CPA(sb + AV(buf ^ 1) + d * 144 + c * 16, (const char*)g_vt + g);
            }
            CPC();
            CPW(1);
        } else {
            CPW(0);
        }
        __syncthreads();

        // ---- S = Q K^T (single pass) ----
        float s[8][4];
        #pragma unroll
        for (int a = 0; a < 8; a++)
            #pragma unroll
            for (int c = 0; c < 4; c++) s[a][c] = 0.0f;
        #pragma unroll
        for (int ks = 0; ks < 8; ks++) {
            u32 qf[4];
            {
                u32 row = wid * 16 + rsel;
                u32 byt = ks * 32 + bsel;
                ldsm4(qf, sb + AQ + row * 272 + byt);
            }
            u32 kf[4][4];
            #pragma unroll
            for (int g = 0; g < 4; g++) {
                u32 krow = ks * 16 + rsel;
                u32 byt = g * 32 + bsel;
                ldsm4t(kf[g], sb + AK(buf) + krow * 144 + byt);
            }
            #pragma unroll
            for (int nt = 0; nt < 8; nt++)
                mmaf(s[nt], qf, &kf[nt >> 1][(nt & 1) * 2]);
        }

        // ---- softmax (no max; exp-safe), pack P single fp16 ----
        const int nvalid = memlen - k0;
        u32 pf[4][4];
        #pragma unroll
        for (int nt = 0; nt < 8; nt++) {
            int j0 = nt * 8 + (lane & 3) * 2;
            float p0 = (j0     < nvalid) ? __expf(s[nt][0]) : 0.0f;
            float p1 = (j0 + 1 < nvalid) ? __expf(s[nt][1]) : 0.0f;
            float p2 = (j0     < nvalid) ? __expf(s[nt][2]) : 0.0f;
            float p3 = (j0 + 1 < nvalid) ? __expf(s[nt][3]) : 0.0f;
            lsum0 += p0 + p1;
            lsum1 += p2 + p3;
            int kt = nt >> 1, half = nt & 1;
            pf[kt][half * 2 + 0] = pk1(p0, p1);
            pf[kt][half * 2 + 1] = pk1(p2, p3);
        }

        // ---- O += P V (single pass) ----
        #pragma unroll
        for (int kt = 0; kt < 4; kt++) {
            #pragma unroll
            for (int nd = 0; nd < 8; nd++) {
                u32 vh[4];
                u32 row = nd * 16 + vrsel;
                u32 byt = kt * 32 + vbsel;
                ldsm4(vh, sb + AV(buf) + row * 144 + byt);
                mmaf(o[2 * nd],     pf[kt], vh);
                mmaf(o[2 * nd + 1], pf[kt], vh + 2);
            }
        }
        __syncthreads();
    }

    // ---- epilogue: unnormalized partials (packed fp16) ----
    lsum0 += __shfl_xor_sync(0xffffffffu, lsum0, 1);
    lsum0 += __shfl_xor_sync(0xffffffffu, lsum0, 2);
    lsum1 += __shfl_xor_sync(0xffffffffu, lsum1, 1);
    lsum1 += __shfl_xor_sync(0xffffffffu, lsum1, 2);
    const int r = q0 + wid * 16 + (lane >> 2);
    #pragma unroll
    for (int nt = 0; nt < 16; nt++) {
        int c = nt * 8 + (lane & 3) * 2;
        g_po[kh][((size_t)(b * LQ_ + r) * DP_ + c) >> 1]     = pk1(o[nt][0], o[nt][1]);
        g_po[kh][((size_t)(b * LQ_ + r + 8) * DP_ + c) >> 1] = pk1(o[nt][2], o[nt][3]);
    }
    if ((lane & 3) == 0) {
        g_pl[kh][b * LQ_ + r]     = lsum0;
        g_pl[kh][b * LQ_ + r + 8] = lsum1;
    }
}

// ---------------- combine: out = sum(O_i)/sum(l_i) over USED splits (8 floats/thread) ----------------
__global__ void __launch_bounds__(256, 8) combine_kernel(
    const int* __restrict__ memlen_arr, float* __restrict__ out)
{
    const size_t i8 = (size_t)blockIdx.x * 256 + threadIdx.x;   // float8 index, 0..262143
    const size_t row = i8 >> 4;
    const int b = (int)(row >> 11);
    const int ntiles = (memlen_arr[b] + 63) >> 6;
    const int ns = (ntiles + 7) >> 3;                           // used splits, 1..4
    float l = 0.0f;
    float w[8] = {0.f, 0.f, 0.f, 0.f, 0.f, 0.f, 0.f, 0.f};
    #pragma unroll 1
    for (int kh = 0; kh < ns; kh++) {
        l += g_pl[kh][row];
        uint4 a = *(const uint4*)&g_po[kh][i8 * 4];
        __half2 h0 = *reinterpret_cast<__half2*>(&a.x);
        __half2 h1 = *reinterpret_cast<__half2*>(&a.y);
        __half2 h2 = *reinterpret_cast<__half2*>(&a.z);
        __half2 h3 = *reinterpret_cast<__half2*>(&a.w);
        w[0] += __low2float(h0); w[1] += __high2float(h0);
        w[2] += __low2float(h1); w[3] += __high2float(h1);
        w[4] += __low2float(h2); w[5] += __high2float(h2);
        w[6] += __low2float(h3); w[7] += __high2float(h3);
    }
    const float inv = 1.0f / l;
    float4 w0 = make_float4(w[0] * inv, w[1] * inv, w[2] * inv, w[3] * inv);
    float4 w1 = make_float4(w[4] * inv, w[5] * inv, w[6] * inv, w[7] * inv);
    *(float4*)&out[i8 * 8]     = w0;
    *(float4*)&out[i8 * 8 + 4] = w1;
}

// ---------------- launch ----------------
extern "C" void kernel_launch(void* const* d_in, const int* in_sizes, int n_in,
                              void* d_out, int out_size)
{
    const float* q  = (const float*)d_in[0];
    const float* k  = (const float*)d_in[1];
    const float* v  = (const float*)d_in[2];
    const int* memlen = (const int*)d_in[3];
    const float* Wq = (const float*)d_in[4];
    const float* Wk = (const float*)d_in[5];
    const float* Wv = (const float*)d_in[6];
    float* out = (float*)d_out;

    dim3 wgrid(128, 3);
    wprep_kernel<<<wgrid, 256>>>(Wq, Wk, Wv);

    cudaFuncSetAttribute(proj_mma, cudaFuncAttributeMaxDynamicSharedMemorySize, PJ_SM);
    dim3 pgrid(128, 3);
    proj_mma<<<pgrid, 256, PJ_SM>>>(q, k, v, memlen);

    cudaFuncSetAttribute(attn_mma, cudaFuncAttributeMaxDynamicSharedMemorySize, A_SM);
    dim3 agrid(16, 8, NSPLIT);
    attn_mma<<<agrid, 256, A_SM>>>(memlen);

    combine_kernel<<<1024, 256>>>(memlen, out);
}